// round 6
// baseline (speedup 1.0000x reference)
#include <cuda_runtime.h>
#include <cstdint>

#define NB      2
#define SEQ     2048
#define DMODEL  1024
#define HEADS   16
#define HD      64
#define MTOT    (NB*SEQ)        // 4096
#define N_QKV   (3*DMODEL)      // 3072

// Scratch (static device globals -- no allocation anywhere)
__device__ float g_qb[NB*HEADS*SEQ*HD];   // [b,h,s,hd]
__device__ float g_kb[NB*HEADS*SEQ*HD];
__device__ float g_vb[NB*HEADS*SEQ*HD];
__device__ float g_ab[MTOT*DMODEL];       // attention out, [b,s,h,hd] == [m, d]

// ---------------- helpers ----------------
__device__ __forceinline__ unsigned f2tf(float x) {
    unsigned u; asm("cvt.rna.tf32.f32 %0, %1;" : "=r"(u) : "f"(x)); return u;
}
__device__ __forceinline__ float f2tff(float x) { return __uint_as_float(f2tf(x)); }

__device__ __forceinline__ void mma8(float c[4],
                                     unsigned a0, unsigned a1, unsigned a2, unsigned a3,
                                     unsigned b0, unsigned b1) {
    asm volatile(
        "mma.sync.aligned.m16n8k8.row.col.f32.tf32.tf32.f32 "
        "{%0,%1,%2,%3}, {%4,%5,%6,%7}, {%8,%9}, {%0,%1,%2,%3};\n"
        : "+f"(c[0]), "+f"(c[1]), "+f"(c[2]), "+f"(c[3])
        : "r"(a0), "r"(a1), "r"(a2), "r"(a3), "r"(b0), "r"(b1));
}

// ---------------- GEMM: C[M,N] = A[M,K] @ B[N,K]^T + bias ----------------
// MODE 0: scatter into q/k/v buffers.  MODE 1: A is g_ab, write C row-major.
// k-slot permutation: mma k-slot t holds logical col 2t, slot t+4 holds 2t+1
// (within each 8-col group) -> all fragment loads are contiguous float2 (LDS.64).
template<int MODE>
__global__ __launch_bounds__(256)
void gemm_kernel(const float* __restrict__ Ain, const float* __restrict__ B,
                 const float* __restrict__ bias, float* __restrict__ C,
                 int M, int N, int K)
{
    __shared__ float As[128*36];
    __shared__ float Bs[128*36];

    const float* A = (MODE == 1) ? g_ab : Ain;

    const int tid  = threadIdx.x;
    const int wid  = tid >> 5, lane = tid & 31;
    const int g    = lane >> 2, t = lane & 3;
    const int wm   = (wid >> 2) * 64;   // 2 warps in m
    const int wn   = (wid & 3) * 32;    // 4 warps in n
    const int m0   = blockIdx.y * 128, n0 = blockIdx.x * 128;

    float acc[4][4][4];
#pragma unroll
    for (int i = 0; i < 4; i++)
#pragma unroll
        for (int j = 0; j < 4; j++)
#pragma unroll
            for (int c = 0; c < 4; c++) acc[i][j][c] = 0.f;

    // register prefetch buffers
    float4 pa[4], pb[4];
    const int row_l = tid >> 3;              // 0..31 within 128 via +i*32
    const int q4    = (tid & 7) << 2;        // col offset 0..28

#pragma unroll
    for (int i = 0; i < 4; i++) {
        int row = row_l + i * 32;
        pa[i] = *reinterpret_cast<const float4*>(&A[(size_t)(m0 + row) * K + q4]);
        pb[i] = *reinterpret_cast<const float4*>(&B[(size_t)(n0 + row) * K + q4]);
    }

    for (int k0 = 0; k0 < K; k0 += 32) {
        // store staged chunk (tf32-rounded) into smem
#pragma unroll
        for (int i = 0; i < 4; i++) {
            int row = row_l + i * 32;
            float4 ta; ta.x = f2tff(pa[i].x); ta.y = f2tff(pa[i].y);
            ta.z = f2tff(pa[i].z); ta.w = f2tff(pa[i].w);
            *reinterpret_cast<float4*>(&As[row * 36 + q4]) = ta;
            float4 tb; tb.x = f2tff(pb[i].x); tb.y = f2tff(pb[i].y);
            tb.z = f2tff(pb[i].z); tb.w = f2tff(pb[i].w);
            *reinterpret_cast<float4*>(&Bs[row * 36 + q4]) = tb;
        }
        __syncthreads();

        // prefetch next chunk while computing this one
        if (k0 + 32 < K) {
            int kn = k0 + 32;
#pragma unroll
            for (int i = 0; i < 4; i++) {
                int row = row_l + i * 32;
                pa[i] = *reinterpret_cast<const float4*>(&A[(size_t)(m0 + row) * K + kn + q4]);
                pb[i] = *reinterpret_cast<const float4*>(&B[(size_t)(n0 + row) * K + kn + q4]);
            }
        }

#pragma unroll
        for (int kk = 0; kk < 4; kk++) {
            unsigned a[4][4], b[4][2];
#pragma unroll
            for (int mf = 0; mf < 4; mf++) {
                int rb = wm + mf * 16;
                float2 a0 = *reinterpret_cast<const float2*>(&As[(rb + g    ) * 36 + kk * 8 + 2 * t]);
                float2 a1 = *reinterpret_cast<const float2*>(&As[(rb + g + 8) * 36 + kk * 8 + 2 * t]);
                a[mf][0] = __float_as_uint(a0.x);
                a[mf][1] = __float_as_uint(a1.x);
                a[mf][2] = __float_as_uint(a0.y);
                a[mf][3] = __float_as_uint(a1.y);
            }
#pragma unroll
            for (int nf = 0; nf < 4; nf++) {
                int nb = wn + nf * 8;
                float2 bv = *reinterpret_cast<const float2*>(&Bs[(nb + g) * 36 + kk * 8 + 2 * t]);
                b[nf][0] = __float_as_uint(bv.x);
                b[nf][1] = __float_as_uint(bv.y);
            }
#pragma unroll
            for (int mf = 0; mf < 4; mf++)
#pragma unroll
                for (int nf = 0; nf < 4; nf++)
                    mma8(acc[mf][nf], a[mf][0], a[mf][1], a[mf][2], a[mf][3],
                         b[nf][0], b[nf][1]);
        }
        __syncthreads();
    }

#pragma unroll
    for (int mf = 0; mf < 4; mf++)
#pragma unroll
        for (int nf = 0; nf < 4; nf++)
#pragma unroll
            for (int c = 0; c < 4; c++) {
                int row = m0 + wm + mf * 16 + g + ((c >= 2) ? 8 : 0);
                int col = n0 + wn + nf * 8 + 2 * t + (c & 1);
                float v = acc[mf][nf][c] + bias[col];
                if (MODE == 0) {
                    int part = col >> 10, nn = col & 1023;
                    int hh = nn >> 6, e = nn & 63;
                    int bb = row >> 11, sq = row & 2047;
                    float* dst = (part == 0) ? g_qb : ((part == 1) ? g_kb : g_vb);
                    dst[(((size_t)(bb * HEADS + hh)) * SEQ + sq) * HD + e] = v;
                } else {
                    C[(size_t)row * N + col] = v;
                }
            }
}

// ---------------- Flash attention v2 ----------------
// 256 threads (8 warps), 128-row q tile, 64-row kv tile.
// Register softmax (quad shuffles); S C-fragment reused directly as P A-fragment
// via the k-slot permutation (slot t <-> logical col 2t).
__global__ __launch_bounds__(256)
void fa_kernel(const int* __restrict__ maskp)
{
    __shared__ float Ks[64 * 68];
    __shared__ float Vs[64 * 68];

    const int tid = threadIdx.x, wid = tid >> 5, lane = tid & 31;
    const int g = lane >> 2, t = lane & 3;
    const int qi = blockIdx.x, bh = blockIdx.y;
    const int causal = (maskp[0] != 0);

    const float* qp = g_qb + ((size_t)bh * SEQ + qi * 128) * HD;
    const float* kp = g_kb + (size_t)bh * SEQ * HD;
    const float* vp = g_vb + (size_t)bh * SEQ * HD;

    const int wr = wid * 16;

    // Q fragments, permuted k-slots: slot t <- col 2t, slot t+4 <- col 2t+1
    unsigned qf[8][4];
#pragma unroll
    for (int kk = 0; kk < 8; kk++) {
        float2 x0 = *reinterpret_cast<const float2*>(&qp[(wr + g    ) * HD + kk * 8 + 2 * t]);
        float2 x1 = *reinterpret_cast<const float2*>(&qp[(wr + g + 8) * HD + kk * 8 + 2 * t]);
        qf[kk][0] = f2tf(x0.x); qf[kk][1] = f2tf(x1.x);
        qf[kk][2] = f2tf(x0.y); qf[kk][3] = f2tf(x1.y);
    }

    float of[8][4];
#pragma unroll
    for (int nf = 0; nf < 8; nf++)
#pragma unroll
        for (int c = 0; c < 4; c++) of[nf][c] = 0.f;

    float m0 = -1e30f, m1 = -1e30f, l0 = 0.f, l1 = 0.f;
    const int row0 = qi * 128 + wr + g;       // this thread's first row (global)
    const int row1 = row0 + 8;

    const int jend = causal ? (2 * qi + 2) : (SEQ / 64);
    for (int j = 0; j < jend; j++) {
        // stage K, V tiles (64 x 64 each, tf32-rounded)
#pragma unroll
        for (int i = 0; i < 4; i++) {
            int lin = tid + i * 256;
            int row = lin >> 4, c4 = (lin & 15) << 2;
            float4 kv = *reinterpret_cast<const float4*>(&kp[((size_t)(j * 64 + row)) * HD + c4]);
            float4 tk; tk.x = f2tff(kv.x); tk.y = f2tff(kv.y); tk.z = f2tff(kv.z); tk.w = f2tff(kv.w);
            *reinterpret_cast<float4*>(&Ks[row * 68 + c4]) = tk;
            float4 vv = *reinterpret_cast<const float4*>(&vp[((size_t)(j * 64 + row)) * HD + c4]);
            float4 tv; tv.x = f2tff(vv.x); tv.y = f2tff(vv.y); tv.z = f2tff(vv.z); tv.w = f2tff(vv.w);
            *reinterpret_cast<float4*>(&Vs[row * 68 + c4]) = tv;
        }
        __syncthreads();

        // S = Q K^T  (k-permutation matches qf)
        float sf[8][4];
#pragma unroll
        for (int nf = 0; nf < 8; nf++)
#pragma unroll
            for (int c = 0; c < 4; c++) sf[nf][c] = 0.f;
#pragma unroll
        for (int kk = 0; kk < 8; kk++) {
#pragma unroll
            for (int nf = 0; nf < 8; nf++) {
                float2 bv = *reinterpret_cast<const float2*>(&Ks[(nf * 8 + g) * 68 + kk * 8 + 2 * t]);
                mma8(sf[nf], qf[kk][0], qf[kk][1], qf[kk][2], qf[kk][3],
                     __float_as_uint(bv.x), __float_as_uint(bv.y));
            }
        }

        // scale + causal mask (only the two diagonal-crossing tiles need it)
        const bool mk = causal && (j >= 2 * qi);
        const int jc = j * 64;
#pragma unroll
        for (int nf = 0; nf < 8; nf++) {
            int c0 = jc + nf * 8 + 2 * t, c1 = c0 + 1;
            sf[nf][0] = (mk && c0 > row0) ? -1e30f : sf[nf][0] * 0.125f;
            sf[nf][1] = (mk && c1 > row0) ? -1e30f : sf[nf][1] * 0.125f;
            sf[nf][2] = (mk && c0 > row1) ? -1e30f : sf[nf][2] * 0.125f;
            sf[nf][3] = (mk && c1 > row1) ? -1e30f : sf[nf][3] * 0.125f;
        }

        // register softmax: row max over 16 local vals + quad shuffle
        float mx0 = -1e30f, mx1 = -1e30f;
#pragma unroll
        for (int nf = 0; nf < 8; nf++) {
            mx0 = fmaxf(mx0, fmaxf(sf[nf][0], sf[nf][1]));
            mx1 = fmaxf(mx1, fmaxf(sf[nf][2], sf[nf][3]));
        }
        mx0 = fmaxf(mx0, __shfl_xor_sync(0xffffffffu, mx0, 1));
        mx0 = fmaxf(mx0, __shfl_xor_sync(0xffffffffu, mx0, 2));
        mx1 = fmaxf(mx1, __shfl_xor_sync(0xffffffffu, mx1, 1));
        mx1 = fmaxf(mx1, __shfl_xor_sync(0xffffffffu, mx1, 2));
        const float nm0 = fmaxf(m0, mx0), nm1 = fmaxf(m1, mx1);

        float sum0 = 0.f, sum1 = 0.f;
#pragma unroll
        for (int nf = 0; nf < 8; nf++) {
            sf[nf][0] = __expf(sf[nf][0] - nm0);
            sf[nf][1] = __expf(sf[nf][1] - nm0);
            sf[nf][2] = __expf(sf[nf][2] - nm1);
            sf[nf][3] = __expf(sf[nf][3] - nm1);
            sum0 += sf[nf][0] + sf[nf][1];
            sum1 += sf[nf][2] + sf[nf][3];
        }
        sum0 += __shfl_xor_sync(0xffffffffu, sum0, 1);
        sum0 += __shfl_xor_sync(0xffffffffu, sum0, 2);
        sum1 += __shfl_xor_sync(0xffffffffu, sum1, 1);
        sum1 += __shfl_xor_sync(0xffffffffu, sum1, 2);

        const float sc0 = __expf(m0 - nm0), sc1 = __expf(m1 - nm1);
        l0 = l0 * sc0 + sum0; l1 = l1 * sc1 + sum1;
        m0 = nm0; m1 = nm1;

        // rescale O, then O += P V.  sf IS the P A-fragment under the
        // k-permutation: slot t = col 2t -> a order {[0],[2],[1],[3]}.
#pragma unroll
        for (int nf = 0; nf < 8; nf++) {
            of[nf][0] *= sc0; of[nf][1] *= sc0; of[nf][2] *= sc1; of[nf][3] *= sc1;
        }
#pragma unroll
        for (int kk = 0; kk < 8; kk++) {
            unsigned a0 = f2tf(sf[kk][0]);
            unsigned a1 = f2tf(sf[kk][2]);
            unsigned a2 = f2tf(sf[kk][1]);
            unsigned a3 = f2tf(sf[kk][3]);
#pragma unroll
            for (int nf = 0; nf < 8; nf++) {
                // V rows permuted to match: slot t <- row kk*8+2t, slot t+4 <- kk*8+2t+1
                unsigned b0 = __float_as_uint(Vs[(kk * 8 + 2 * t    ) * 68 + nf * 8 + g]);
                unsigned b1 = __float_as_uint(Vs[(kk * 8 + 2 * t + 1) * 68 + nf * 8 + g]);
                mma8(of[nf], a0, a1, a2, a3, b0, b1);
            }
        }
        __syncthreads();
    }

    // normalize and write: out layout [b, s, h, hd]
    const float il0 = 1.f / l0, il1 = 1.f / l1;
    const int b = bh >> 4, h = bh & 15;
    const int sq0 = qi * 128 + wr + g, sq1 = sq0 + 8;
#pragma unroll
    for (int nf = 0; nf < 8; nf++) {
        int col = nf * 8 + 2 * t;
        float2 v0; v0.x = of[nf][0] * il0; v0.y = of[nf][1] * il0;
        float2 v1; v1.x = of[nf][2] * il1; v1.y = of[nf][3] * il1;
        *reinterpret_cast<float2*>(&g_ab[(((size_t)b * SEQ + sq0) * HEADS + h) * HD + col]) = v0;
        *reinterpret_cast<float2*>(&g_ab[(((size_t)b * SEQ + sq1) * HEADS + h) * HD + col]) = v1;
    }
}

// ---------------- launch ----------------
extern "C" void kernel_launch(void* const* d_in, const int* in_sizes, int n_in,
                              void* d_out, int out_size)
{
    const float* x    = (const float*)d_in[0];
    const float* Wqkv = (const float*)d_in[1];
    const float* bqkv = (const float*)d_in[2];
    const float* Wd   = (const float*)d_in[3];
    const float* bd   = (const float*)d_in[4];
    const int*   mask = (const int*)d_in[5];
    float* out = (float*)d_out;

    gemm_kernel<0><<<dim3(N_QKV / 128, MTOT / 128), 256>>>(
        x, Wqkv, bqkv, nullptr, MTOT, N_QKV, DMODEL);

    fa_kernel<<<dim3(SEQ / 128, NB * HEADS), 256>>>(mask);

    gemm_kernel<1><<<dim3(DMODEL / 128, MTOT / 128), 256>>>(
        nullptr, Wd, bd, out, MTOT, DMODEL, DMODEL);
}

// round 8
// speedup vs baseline: 1.1221x; 1.1221x over previous
#include <cuda_runtime.h>
#include <cstdint>

#define NB      2
#define SEQ     2048
#define DMODEL  1024
#define HEADS   16
#define HD      64
#define MTOT    (NB*SEQ)        // 4096
#define N_QKV   (3*DMODEL)      // 3072

// Scratch (static device globals -- no allocation anywhere)
__device__ float g_qb[NB*HEADS*SEQ*HD];   // [b,h,s,hd]
__device__ float g_kb[NB*HEADS*SEQ*HD];
__device__ float g_vb[NB*HEADS*SEQ*HD];
__device__ float g_ab[MTOT*DMODEL];       // attention out, [b,s,h,hd] == [m, d]

// ---------------- helpers ----------------
__device__ __forceinline__ unsigned f2tf(float x) {
    unsigned u; asm("cvt.rna.tf32.f32 %0, %1;" : "=r"(u) : "f"(x)); return u;
}
__device__ __forceinline__ float f2tff(float x) { return __uint_as_float(f2tf(x)); }

__device__ __forceinline__ void mma8(float c[4],
                                     unsigned a0, unsigned a1, unsigned a2, unsigned a3,
                                     unsigned b0, unsigned b1) {
    asm volatile(
        "mma.sync.aligned.m16n8k8.row.col.f32.tf32.tf32.f32 "
        "{%0,%1,%2,%3}, {%4,%5,%6,%7}, {%8,%9}, {%0,%1,%2,%3};\n"
        : "+f"(c[0]), "+f"(c[1]), "+f"(c[2]), "+f"(c[3])
        : "r"(a0), "r"(a1), "r"(a2), "r"(a3), "r"(b0), "r"(b1));
}

// ---------------- GEMM: C[M,N] = A[M,K] @ B[N,K]^T + bias ----------------
// MODE 0: scatter into q/k/v buffers.  MODE 1: A is g_ab, write C row-major.
// (R0 version: 32-bit stride-36 fragment loads, conflict-free. Do not change.)
template<int MODE>
__global__ __launch_bounds__(256)
void gemm_kernel(const float* __restrict__ Ain, const float* __restrict__ B,
                 const float* __restrict__ bias, float* __restrict__ C,
                 int M, int N, int K)
{
    __shared__ float As[128*36];
    __shared__ float Bs[128*36];

    const float* A = (MODE == 1) ? g_ab : Ain;

    const int tid  = threadIdx.x;
    const int wid  = tid >> 5, lane = tid & 31;
    const int g    = lane >> 2, t = lane & 3;
    const int wm   = (wid >> 2) * 64;   // 2 warps in m
    const int wn   = (wid & 3) * 32;    // 4 warps in n
    const int m0   = blockIdx.y * 128, n0 = blockIdx.x * 128;

    float acc[4][4][4];
#pragma unroll
    for (int i = 0; i < 4; i++)
#pragma unroll
        for (int j = 0; j < 4; j++)
#pragma unroll
            for (int c = 0; c < 4; c++) acc[i][j][c] = 0.f;

    for (int k0 = 0; k0 < K; k0 += 32) {
#pragma unroll
        for (int i = 0; i < 4; i++) {
            int lin = tid + i * 256;                 // float4 index
            int row = lin >> 3, c4 = (lin & 7) << 2; // 8 float4 per row
            float4 va = *reinterpret_cast<const float4*>(&A[(size_t)(m0 + row) * K + k0 + c4]);
            float4 ta; ta.x = f2tff(va.x); ta.y = f2tff(va.y); ta.z = f2tff(va.z); ta.w = f2tff(va.w);
            *reinterpret_cast<float4*>(&As[row * 36 + c4]) = ta;
            float4 vb = *reinterpret_cast<const float4*>(&B[(size_t)(n0 + row) * K + k0 + c4]);
            float4 tb; tb.x = f2tff(vb.x); tb.y = f2tff(vb.y); tb.z = f2tff(vb.z); tb.w = f2tff(vb.w);
            *reinterpret_cast<float4*>(&Bs[row * 36 + c4]) = tb;
        }
        __syncthreads();
#pragma unroll
        for (int kk = 0; kk < 4; kk++) {
            unsigned a[4][4], b[4][2];
#pragma unroll
            for (int mf = 0; mf < 4; mf++) {
                int rb = wm + mf * 16;
                a[mf][0] = __float_as_uint(As[(rb + g    ) * 36 + kk * 8 + t    ]);
                a[mf][1] = __float_as_uint(As[(rb + g + 8) * 36 + kk * 8 + t    ]);
                a[mf][2] = __float_as_uint(As[(rb + g    ) * 36 + kk * 8 + t + 4]);
                a[mf][3] = __float_as_uint(As[(rb + g + 8) * 36 + kk * 8 + t + 4]);
            }
#pragma unroll
            for (int nf = 0; nf < 4; nf++) {
                int nb = wn + nf * 8;
                b[nf][0] = __float_as_uint(Bs[(nb + g) * 36 + kk * 8 + t    ]);
                b[nf][1] = __float_as_uint(Bs[(nb + g) * 36 + kk * 8 + t + 4]);
            }
#pragma unroll
            for (int mf = 0; mf < 4; mf++)
#pragma unroll
                for (int nf = 0; nf < 4; nf++)
                    mma8(acc[mf][nf], a[mf][0], a[mf][1], a[mf][2], a[mf][3],
                         b[nf][0], b[nf][1]);
        }
        __syncthreads();
    }

#pragma unroll
    for (int mf = 0; mf < 4; mf++)
#pragma unroll
        for (int nf = 0; nf < 4; nf++)
#pragma unroll
            for (int c = 0; c < 4; c++) {
                int row = m0 + wm + mf * 16 + g + ((c >= 2) ? 8 : 0);
                int col = n0 + wn + nf * 8 + 2 * t + (c & 1);
                float v = acc[mf][nf][c] + bias[col];
                if (MODE == 0) {
                    int part = col >> 10, nn = col & 1023;
                    int hh = nn >> 6, e = nn & 63;
                    int bb = row >> 11, sq = row & 2047;
                    float* dst = (part == 0) ? g_qb : ((part == 1) ? g_kb : g_vb);
                    dst[(((size_t)(bb * HEADS + hh)) * SEQ + sq) * HD + e] = v;
                } else {
                    C[(size_t)row * N + col] = v;
                }
            }
}

// ---------------- Flash attention ----------------
// Block = 128 threads (4 warps), one 64-row q tile for one (b,h).
// Register softmax on S C-fragments (quad shuffles); m/l in registers.
// P overwrites the K smem tile, but only AFTER a block barrier confirms all
// warps finished their S mma (every warp reads ALL 64 K rows -- the R6 race).
// The P-write -> PV A-fragment read edge IS warp-local (own 16 rows), so only
// __syncwarp there.
__global__ __launch_bounds__(128)
void fa_kernel(const int* __restrict__ maskp)
{
    __shared__ float KS[64 * 68];   // K tile, then reused as P tile
    __shared__ float Vs[64 * 68];

    const int tid = threadIdx.x, wid = tid >> 5, lane = tid & 31;
    const int g = lane >> 2, t = lane & 3;
    const int qi = blockIdx.x, bh = blockIdx.y;
    const int causal = (maskp[0] != 0);

    const float* qp = g_qb + ((size_t)bh * SEQ + qi * 64) * HD;
    const float* kp = g_kb + (size_t)bh * SEQ * HD;
    const float* vp = g_vb + (size_t)bh * SEQ * HD;

    const int wr = wid * 16;

    // Q fragments resident in registers (tf32), standard slots
    unsigned qf[8][4];
#pragma unroll
    for (int kk = 0; kk < 8; kk++) {
        qf[kk][0] = f2tf(qp[(wr + g    ) * HD + kk * 8 + t    ]);
        qf[kk][1] = f2tf(qp[(wr + g + 8) * HD + kk * 8 + t    ]);
        qf[kk][2] = f2tf(qp[(wr + g    ) * HD + kk * 8 + t + 4]);
        qf[kk][3] = f2tf(qp[(wr + g + 8) * HD + kk * 8 + t + 4]);
    }

    float of[8][4];
#pragma unroll
    for (int nf = 0; nf < 8; nf++)
#pragma unroll
        for (int c = 0; c < 4; c++) of[nf][c] = 0.f;

    // per-thread softmax state: rows wr+g (0) and wr+g+8 (1)
    float m0 = -1e30f, m1 = -1e30f, l0 = 0.f, l1 = 0.f;
    const int row0 = wr + g, row1 = wr + g + 8;   // tile-local rows

    const int jend = causal ? (qi + 1) : (SEQ / 64);
    for (int j = 0; j < jend; j++) {
        // stage K, V tiles (tf32-rounded)
#pragma unroll
        for (int i = 0; i < 8; i++) {
            int lin = tid + i * 128;
            int row = lin >> 4, c4 = (lin & 15) << 2;
            float4 kv = *reinterpret_cast<const float4*>(&kp[((size_t)(j * 64 + row)) * HD + c4]);
            float4 tk; tk.x = f2tff(kv.x); tk.y = f2tff(kv.y); tk.z = f2tff(kv.z); tk.w = f2tff(kv.w);
            *reinterpret_cast<float4*>(&KS[row * 68 + c4]) = tk;
            float4 vv = *reinterpret_cast<const float4*>(&vp[((size_t)(j * 64 + row)) * HD + c4]);
            float4 tv; tv.x = f2tff(vv.x); tv.y = f2tff(vv.y); tv.z = f2tff(vv.z); tv.w = f2tff(vv.w);
            *reinterpret_cast<float4*>(&Vs[row * 68 + c4]) = tv;
        }
        __syncthreads();

        // S = Q K^T  (standard 32-bit conflict-free fragment loads)
        float sf[8][4];
#pragma unroll
        for (int nf = 0; nf < 8; nf++)
#pragma unroll
            for (int c = 0; c < 4; c++) sf[nf][c] = 0.f;
#pragma unroll
        for (int kk = 0; kk < 8; kk++) {
#pragma unroll
            for (int nf = 0; nf < 8; nf++) {
                unsigned b0 = __float_as_uint(KS[(nf * 8 + g) * 68 + kk * 8 + t    ]);
                unsigned b1 = __float_as_uint(KS[(nf * 8 + g) * 68 + kk * 8 + t + 4]);
                mma8(sf[nf], qf[kk][0], qf[kk][1], qf[kk][2], qf[kk][3], b0, b1);
            }
        }

        // scale + causal mask in registers
        // thread's S cols: nf*8 + 2t + {0,1}; rows row0 (c0,c1) / row1 (c2,c3)
        const bool mk = causal && (j == qi);
#pragma unroll
        for (int nf = 0; nf < 8; nf++) {
            int c0 = nf * 8 + 2 * t, c1 = c0 + 1;
            sf[nf][0] = (mk && c0 > row0) ? -1e30f : sf[nf][0] * 0.125f;
            sf[nf][1] = (mk && c1 > row0) ? -1e30f : sf[nf][1] * 0.125f;
            sf[nf][2] = (mk && c0 > row1) ? -1e30f : sf[nf][2] * 0.125f;
            sf[nf][3] = (mk && c1 > row1) ? -1e30f : sf[nf][3] * 0.125f;
        }

        // register softmax: row reduction across the t-quad
        float mx0 = -1e30f, mx1 = -1e30f;
#pragma unroll
        for (int nf = 0; nf < 8; nf++) {
            mx0 = fmaxf(mx0, fmaxf(sf[nf][0], sf[nf][1]));
            mx1 = fmaxf(mx1, fmaxf(sf[nf][2], sf[nf][3]));
        }
        mx0 = fmaxf(mx0, __shfl_xor_sync(0xffffffffu, mx0, 1));
        mx0 = fmaxf(mx0, __shfl_xor_sync(0xffffffffu, mx0, 2));
        mx1 = fmaxf(mx1, __shfl_xor_sync(0xffffffffu, mx1, 1));
        mx1 = fmaxf(mx1, __shfl_xor_sync(0xffffffffu, mx1, 2));
        const float nm0 = fmaxf(m0, mx0), nm1 = fmaxf(m1, mx1);

        float sum0 = 0.f, sum1 = 0.f;
#pragma unroll
        for (int nf = 0; nf < 8; nf++) {
            sf[nf][0] = __expf(sf[nf][0] - nm0);
            sf[nf][1] = __expf(sf[nf][1] - nm0);
            sf[nf][2] = __expf(sf[nf][2] - nm1);
            sf[nf][3] = __expf(sf[nf][3] - nm1);
            sum0 += sf[nf][0] + sf[nf][1];
            sum1 += sf[nf][2] + sf[nf][3];
        }
        sum0 += __shfl_xor_sync(0xffffffffu, sum0, 1);
        sum0 += __shfl_xor_sync(0xffffffffu, sum0, 2);
        sum1 += __shfl_xor_sync(0xffffffffu, sum1, 1);
        sum1 += __shfl_xor_sync(0xffffffffu, sum1, 2);

        const float sc0 = __expf(m0 - nm0), sc1 = __expf(m1 - nm1);
        l0 = l0 * sc0 + sum0; l1 = l1 * sc1 + sum1;
        m0 = nm0; m1 = nm1;

        // ALL warps must be done reading K (every warp reads all 64 KS rows in
        // its S mma) before anyone overwrites KS with P.
        __syncthreads();

#pragma unroll
        for (int nf = 0; nf < 8; nf++) {
            int c0 = nf * 8 + 2 * t;
            KS[row0 * 68 + c0    ] = sf[nf][0];
            KS[row0 * 68 + c0 + 1] = sf[nf][1];
            KS[row1 * 68 + c0    ] = sf[nf][2];
            KS[row1 * 68 + c0 + 1] = sf[nf][3];
        }
        __syncwarp();   // PV A-fragments below read only this warp's 16 rows

        // rescale O, then O += P V
#pragma unroll
        for (int nf = 0; nf < 8; nf++) {
            of[nf][0] *= sc0; of[nf][1] *= sc0; of[nf][2] *= sc1; of[nf][3] *= sc1;
        }
#pragma unroll
        for (int kk = 0; kk < 8; kk++) {
            unsigned a0 = f2tf(KS[(wr + g    ) * 68 + kk * 8 + t    ]);
            unsigned a1 = f2tf(KS[(wr + g + 8) * 68 + kk * 8 + t    ]);
            unsigned a2 = f2tf(KS[(wr + g    ) * 68 + kk * 8 + t + 4]);
            unsigned a3 = f2tf(KS[(wr + g + 8) * 68 + kk * 8 + t + 4]);
#pragma unroll
            for (int nf = 0; nf < 8; nf++) {
                unsigned b0 = __float_as_uint(Vs[(kk * 8 + t    ) * 68 + nf * 8 + g]);
                unsigned b1 = __float_as_uint(Vs[(kk * 8 + t + 4) * 68 + nf * 8 + g]);
                mma8(of[nf], a0, a1, a2, a3, b0, b1);
            }
        }
        __syncthreads();   // everyone done with KS/Vs before next staging
    }

    // normalize and write: out layout [b, s, h, hd] == [m, d]
    const float il0 = 1.f / l0, il1 = 1.f / l1;
    const int b = bh >> 4, h = bh & 15;
    const int sq0 = qi * 64 + row0, sq1 = qi * 64 + row1;
#pragma unroll
    for (int nf = 0; nf < 8; nf++) {
        int col = nf * 8 + 2 * t;
        float2 v0; v0.x = of[nf][0] * il0; v0.y = of[nf][1] * il0;
        float2 v1; v1.x = of[nf][2] * il1; v1.y = of[nf][3] * il1;
        *reinterpret_cast<float2*>(&g_ab[(((size_t)b * SEQ + sq0) * HEADS + h) * HD + col]) = v0;
        *reinterpret_cast<float2*>(&g_ab[(((size_t)b * SEQ + sq1) * HEADS + h) * HD + col]) = v1;
    }
}

// ---------------- launch ----------------
extern "C" void kernel_launch(void* const* d_in, const int* in_sizes, int n_in,
                              void* d_out, int out_size)
{
    const float* x    = (const float*)d_in[0];
    const float* Wqkv = (const float*)d_in[1];
    const float* bqkv = (const float*)d_in[2];
    const float* Wd   = (const float*)d_in[3];
    const float* bd   = (const float*)d_in[4];
    const int*   mask = (const int*)d_in[5];
    float* out = (float*)d_out;

    gemm_kernel<0><<<dim3(N_QKV / 128, MTOT / 128), 256>>>(
        x, Wqkv, bqkv, nullptr, MTOT, N_QKV, DMODEL);

    fa_kernel<<<dim3(SEQ / 64, NB * HEADS), 128>>>(mask);

    gemm_kernel<1><<<dim3(DMODEL / 128, MTOT / 128), 256>>>(
        nullptr, Wd, bd, out, MTOT, DMODEL, DMODEL);
}

// round 9
// speedup vs baseline: 1.2845x; 1.1447x over previous
#include <cuda_runtime.h>
#include <cstdint>

#define NB      2
#define SEQ     2048
#define DMODEL  1024
#define HEADS   16
#define HD      64
#define MTOT    (NB*SEQ)        // 4096
#define N_QKV   (3*DMODEL)      // 3072

// Scratch (static device globals -- no allocation anywhere)
__device__ float g_qb[NB*HEADS*SEQ*HD];   // [b,h,s,hd]
__device__ float g_kb[NB*HEADS*SEQ*HD];
__device__ float g_vb[NB*HEADS*SEQ*HD];
__device__ float g_ab[MTOT*DMODEL];       // attention out, [b,s,h,hd] == [m, d]

// ---------------- helpers ----------------
__device__ __forceinline__ unsigned f2tf(float x) {
    unsigned u; asm("cvt.rna.tf32.f32 %0, %1;" : "=r"(u) : "f"(x)); return u;
}
__device__ __forceinline__ float f2tff(float x) { return __uint_as_float(f2tf(x)); }

__device__ __forceinline__ void mma8(float c[4],
                                     unsigned a0, unsigned a1, unsigned a2, unsigned a3,
                                     unsigned b0, unsigned b1) {
    asm volatile(
        "mma.sync.aligned.m16n8k8.row.col.f32.tf32.tf32.f32 "
        "{%0,%1,%2,%3}, {%4,%5,%6,%7}, {%8,%9}, {%0,%1,%2,%3};\n"
        : "+f"(c[0]), "+f"(c[1]), "+f"(c[2]), "+f"(c[3])
        : "r"(a0), "r"(a1), "r"(a2), "r"(a3), "r"(b0), "r"(b1));
}

// ---------------- GEMM: C[M,N] = A[M,K] @ B[N,K]^T + bias ----------------
// MODE 0: scatter into q/k/v buffers.  MODE 1: A is g_ab, write C row-major.
// R0 fragment pattern (32-bit, stride-36, conflict-free) + double-buffered
// smem so LDG of chunk k+1 overlaps the mma block of chunk k. 1 barrier/chunk.
#define GEMM_SMEM_BYTES (4 * 128 * 36 * 4)   // 2 stages x (A+B) x 128x36 floats

template<int MODE>
__global__ __launch_bounds__(256)
void gemm_kernel(const float* __restrict__ Ain, const float* __restrict__ B,
                 const float* __restrict__ bias, float* __restrict__ C,
                 int M, int N, int K)
{
    extern __shared__ float gsm[];
    float* Abuf[2] = { gsm,            gsm + 128 * 36 };
    float* Bbuf[2] = { gsm + 2 * 128 * 36, gsm + 3 * 128 * 36 };

    const float* A = (MODE == 1) ? g_ab : Ain;

    const int tid  = threadIdx.x;
    const int wid  = tid >> 5, lane = tid & 31;
    const int g    = lane >> 2, t = lane & 3;
    const int wm   = (wid >> 2) * 64;   // 2 warps in m
    const int wn   = (wid & 3) * 32;    // 4 warps in n
    const int m0   = blockIdx.y * 128, n0 = blockIdx.x * 128;

    // staging indices (each thread moves 4 float4s of A and 4 of B per chunk)
    int srow[4], scol[4];
#pragma unroll
    for (int i = 0; i < 4; i++) {
        int lin = tid + i * 256;
        srow[i] = lin >> 3;
        scol[i] = (lin & 7) << 2;
    }

    float acc[4][4][4];
#pragma unroll
    for (int i = 0; i < 4; i++)
#pragma unroll
        for (int j = 0; j < 4; j++)
#pragma unroll
            for (int c = 0; c < 4; c++) acc[i][j][c] = 0.f;

    // prefetch chunk 0 and store to stage 0
    float4 pa[4], pb[4];
#pragma unroll
    for (int i = 0; i < 4; i++) {
        pa[i] = *reinterpret_cast<const float4*>(&A[(size_t)(m0 + srow[i]) * K + scol[i]]);
        pb[i] = *reinterpret_cast<const float4*>(&B[(size_t)(n0 + srow[i]) * K + scol[i]]);
    }
#pragma unroll
    for (int i = 0; i < 4; i++) {
        float4 ta; ta.x = f2tff(pa[i].x); ta.y = f2tff(pa[i].y); ta.z = f2tff(pa[i].z); ta.w = f2tff(pa[i].w);
        *reinterpret_cast<float4*>(&Abuf[0][srow[i] * 36 + scol[i]]) = ta;
        float4 tb; tb.x = f2tff(pb[i].x); tb.y = f2tff(pb[i].y); tb.z = f2tff(pb[i].z); tb.w = f2tff(pb[i].w);
        *reinterpret_cast<float4*>(&Bbuf[0][srow[i] * 36 + scol[i]]) = tb;
    }
    __syncthreads();

    const int NCH = K / 32;
    for (int ch = 0; ch < NCH; ch++) {
        const int cur = ch & 1, nxt = cur ^ 1;
        const float* As = Abuf[cur];
        const float* Bs = Bbuf[cur];

        // issue LDGs for next chunk before the mma block (latency hidden)
        if (ch + 1 < NCH) {
            const int kn = (ch + 1) * 32;
#pragma unroll
            for (int i = 0; i < 4; i++) {
                pa[i] = *reinterpret_cast<const float4*>(&A[(size_t)(m0 + srow[i]) * K + kn + scol[i]]);
                pb[i] = *reinterpret_cast<const float4*>(&B[(size_t)(n0 + srow[i]) * K + kn + scol[i]]);
            }
        }

#pragma unroll
        for (int kk = 0; kk < 4; kk++) {
            unsigned a[4][4], b[4][2];
#pragma unroll
            for (int mf = 0; mf < 4; mf++) {
                int rb = wm + mf * 16;
                a[mf][0] = __float_as_uint(As[(rb + g    ) * 36 + kk * 8 + t    ]);
                a[mf][1] = __float_as_uint(As[(rb + g + 8) * 36 + kk * 8 + t    ]);
                a[mf][2] = __float_as_uint(As[(rb + g    ) * 36 + kk * 8 + t + 4]);
                a[mf][3] = __float_as_uint(As[(rb + g + 8) * 36 + kk * 8 + t + 4]);
            }
#pragma unroll
            for (int nf = 0; nf < 4; nf++) {
                int nb = wn + nf * 8;
                b[nf][0] = __float_as_uint(Bs[(nb + g) * 36 + kk * 8 + t    ]);
                b[nf][1] = __float_as_uint(Bs[(nb + g) * 36 + kk * 8 + t + 4]);
            }
#pragma unroll
            for (int mf = 0; mf < 4; mf++)
#pragma unroll
                for (int nf = 0; nf < 4; nf++)
                    mma8(acc[mf][nf], a[mf][0], a[mf][1], a[mf][2], a[mf][3],
                         b[nf][0], b[nf][1]);
        }

        if (ch + 1 < NCH) {
            // store next chunk into the other stage (nobody reads it now)
#pragma unroll
            for (int i = 0; i < 4; i++) {
                float4 ta; ta.x = f2tff(pa[i].x); ta.y = f2tff(pa[i].y); ta.z = f2tff(pa[i].z); ta.w = f2tff(pa[i].w);
                *reinterpret_cast<float4*>(&Abuf[nxt][srow[i] * 36 + scol[i]]) = ta;
                float4 tb; tb.x = f2tff(pb[i].x); tb.y = f2tff(pb[i].y); tb.z = f2tff(pb[i].z); tb.w = f2tff(pb[i].w);
                *reinterpret_cast<float4*>(&Bbuf[nxt][srow[i] * 36 + scol[i]]) = tb;
            }
            __syncthreads();
        }
    }

#pragma unroll
    for (int mf = 0; mf < 4; mf++)
#pragma unroll
        for (int nf = 0; nf < 4; nf++)
#pragma unroll
            for (int c = 0; c < 4; c++) {
                int row = m0 + wm + mf * 16 + g + ((c >= 2) ? 8 : 0);
                int col = n0 + wn + nf * 8 + 2 * t + (c & 1);
                float v = acc[mf][nf][c] + bias[col];
                if (MODE == 0) {
                    int part = col >> 10, nn = col & 1023;
                    int hh = nn >> 6, e = nn & 63;
                    int bb = row >> 11, sq = row & 2047;
                    float* dst = (part == 0) ? g_qb : ((part == 1) ? g_kb : g_vb);
                    dst[(((size_t)(bb * HEADS + hh)) * SEQ + sq) * HD + e] = v;
                } else {
                    C[(size_t)row * N + col] = v;
                }
            }
}

// ---------------- Flash attention ----------------
// Block = 128 threads (4 warps). CTA x=p handles q-tiles {p, 31-p}: with the
// causal mask every CTA does exactly 33 kv-tile iterations (load-balanced).
// Register softmax on S C-fragments; P has its OWN smem buffer so no barrier
// is needed between the S mma (K reads) and the P store. 2 barriers/iter.
#define FA_SMEM_BYTES (3 * 64 * 68 * 4)

__global__ __launch_bounds__(128)
void fa_kernel(const int* __restrict__ maskp)
{
    extern __shared__ float fsm[];
    float* Ks = fsm;
    float* Vs = fsm + 64 * 68;
    float* Ps = fsm + 2 * 64 * 68;

    const int tid = threadIdx.x, wid = tid >> 5, lane = tid & 31;
    const int g = lane >> 2, t = lane & 3;
    const int bh = blockIdx.y;
    const int causal = (maskp[0] != 0);

    const float* kp = g_kb + (size_t)bh * SEQ * HD;
    const float* vp = g_vb + (size_t)bh * SEQ * HD;
    const int wr = wid * 16;
    const int row0 = wr + g, row1 = wr + g + 8;   // tile-local rows
    const int b = bh >> 4, h = bh & 15;

    for (int sub = 0; sub < 2; sub++) {
        const int qi = sub ? (31 - (int)blockIdx.x) : (int)blockIdx.x;
        const float* qp = g_qb + ((size_t)bh * SEQ + qi * 64) * HD;

        // Q fragments resident in registers (tf32)
        unsigned qf[8][4];
#pragma unroll
        for (int kk = 0; kk < 8; kk++) {
            qf[kk][0] = f2tf(qp[(wr + g    ) * HD + kk * 8 + t    ]);
            qf[kk][1] = f2tf(qp[(wr + g + 8) * HD + kk * 8 + t    ]);
            qf[kk][2] = f2tf(qp[(wr + g    ) * HD + kk * 8 + t + 4]);
            qf[kk][3] = f2tf(qp[(wr + g + 8) * HD + kk * 8 + t + 4]);
        }

        float of[8][4];
#pragma unroll
        for (int nf = 0; nf < 8; nf++)
#pragma unroll
            for (int c = 0; c < 4; c++) of[nf][c] = 0.f;

        float m0 = -1e30f, m1 = -1e30f, l0 = 0.f, l1 = 0.f;

        const int jend = causal ? (qi + 1) : (SEQ / 64);
        for (int j = 0; j < jend; j++) {
            // stage K, V tiles (tf32-rounded)
#pragma unroll
            for (int i = 0; i < 8; i++) {
                int lin = tid + i * 128;
                int row = lin >> 4, c4 = (lin & 15) << 2;
                float4 kv = *reinterpret_cast<const float4*>(&kp[((size_t)(j * 64 + row)) * HD + c4]);
                float4 tk; tk.x = f2tff(kv.x); tk.y = f2tff(kv.y); tk.z = f2tff(kv.z); tk.w = f2tff(kv.w);
                *reinterpret_cast<float4*>(&Ks[row * 68 + c4]) = tk;
                float4 vv = *reinterpret_cast<const float4*>(&vp[((size_t)(j * 64 + row)) * HD + c4]);
                float4 tv; tv.x = f2tff(vv.x); tv.y = f2tff(vv.y); tv.z = f2tff(vv.z); tv.w = f2tff(vv.w);
                *reinterpret_cast<float4*>(&Vs[row * 68 + c4]) = tv;
            }
            __syncthreads();

            // S = Q K^T
            float sf[8][4];
#pragma unroll
            for (int nf = 0; nf < 8; nf++)
#pragma unroll
                for (int c = 0; c < 4; c++) sf[nf][c] = 0.f;
#pragma unroll
            for (int kk = 0; kk < 8; kk++) {
#pragma unroll
                for (int nf = 0; nf < 8; nf++) {
                    unsigned b0 = __float_as_uint(Ks[(nf * 8 + g) * 68 + kk * 8 + t    ]);
                    unsigned b1 = __float_as_uint(Ks[(nf * 8 + g) * 68 + kk * 8 + t + 4]);
                    mma8(sf[nf], qf[kk][0], qf[kk][1], qf[kk][2], qf[kk][3], b0, b1);
                }
            }

            // scale + causal mask in registers
            const bool mk = causal && (j == qi);
#pragma unroll
            for (int nf = 0; nf < 8; nf++) {
                int c0 = nf * 8 + 2 * t, c1 = c0 + 1;
                sf[nf][0] = (mk && c0 > row0) ? -1e30f : sf[nf][0] * 0.125f;
                sf[nf][1] = (mk && c1 > row0) ? -1e30f : sf[nf][1] * 0.125f;
                sf[nf][2] = (mk && c0 > row1) ? -1e30f : sf[nf][2] * 0.125f;
                sf[nf][3] = (mk && c1 > row1) ? -1e30f : sf[nf][3] * 0.125f;
            }

            // register softmax: row reduction across the t-quad
            float mx0 = -1e30f, mx1 = -1e30f;
#pragma unroll
            for (int nf = 0; nf < 8; nf++) {
                mx0 = fmaxf(mx0, fmaxf(sf[nf][0], sf[nf][1]));
                mx1 = fmaxf(mx1, fmaxf(sf[nf][2], sf[nf][3]));
            }
            mx0 = fmaxf(mx0, __shfl_xor_sync(0xffffffffu, mx0, 1));
            mx0 = fmaxf(mx0, __shfl_xor_sync(0xffffffffu, mx0, 2));
            mx1 = fmaxf(mx1, __shfl_xor_sync(0xffffffffu, mx1, 1));
            mx1 = fmaxf(mx1, __shfl_xor_sync(0xffffffffu, mx1, 2));
            const float nm0 = fmaxf(m0, mx0), nm1 = fmaxf(m1, mx1);

            float sum0 = 0.f, sum1 = 0.f;
#pragma unroll
            for (int nf = 0; nf < 8; nf++) {
                sf[nf][0] = __expf(sf[nf][0] - nm0);
                sf[nf][1] = __expf(sf[nf][1] - nm0);
                sf[nf][2] = __expf(sf[nf][2] - nm1);
                sf[nf][3] = __expf(sf[nf][3] - nm1);
                sum0 += sf[nf][0] + sf[nf][1];
                sum1 += sf[nf][2] + sf[nf][3];
            }
            sum0 += __shfl_xor_sync(0xffffffffu, sum0, 1);
            sum0 += __shfl_xor_sync(0xffffffffu, sum0, 2);
            sum1 += __shfl_xor_sync(0xffffffffu, sum1, 1);
            sum1 += __shfl_xor_sync(0xffffffffu, sum1, 2);

            const float sc0 = __expf(m0 - nm0), sc1 = __expf(m1 - nm1);
            l0 = l0 * sc0 + sum0; l1 = l1 * sc1 + sum1;
            m0 = nm0; m1 = nm1;

            // P goes to its own buffer: no cross-warp hazard with K reads.
#pragma unroll
            for (int nf = 0; nf < 8; nf++) {
                int c0 = nf * 8 + 2 * t;
                Ps[row0 * 68 + c0    ] = sf[nf][0];
                Ps[row0 * 68 + c0 + 1] = sf[nf][1];
                Ps[row1 * 68 + c0    ] = sf[nf][2];
                Ps[row1 * 68 + c0 + 1] = sf[nf][3];
            }
            __syncwarp();   // PV A-fragments read only this warp's 16 rows

            // rescale O, then O += P V
#pragma unroll
            for (int nf = 0; nf < 8; nf++) {
                of[nf][0] *= sc0; of[nf][1] *= sc0; of[nf][2] *= sc1; of[nf][3] *= sc1;
            }
#pragma unroll
            for (int kk = 0; kk < 8; kk++) {
                unsigned a0 = f2tf(Ps[(wr + g    ) * 68 + kk * 8 + t    ]);
                unsigned a1 = f2tf(Ps[(wr + g + 8) * 68 + kk * 8 + t    ]);
                unsigned a2 = f2tf(Ps[(wr + g    ) * 68 + kk * 8 + t + 4]);
                unsigned a3 = f2tf(Ps[(wr + g + 8) * 68 + kk * 8 + t + 4]);
#pragma unroll
                for (int nf = 0; nf < 8; nf++) {
                    unsigned b0 = __float_as_uint(Vs[(kk * 8 + t    ) * 68 + nf * 8 + g]);
                    unsigned b1 = __float_as_uint(Vs[(kk * 8 + t + 4) * 68 + nf * 8 + g]);
                    mma8(of[nf], a0, a1, a2, a3, b0, b1);
                }
            }
            __syncthreads();   // Vs/Ks reads done before next staging
        }

        // normalize and write: out layout [b, s, h, hd] == [m, d]
        const float il0 = 1.f / l0, il1 = 1.f / l1;
        const int sq0 = qi * 64 + row0, sq1 = qi * 64 + row1;
#pragma unroll
        for (int nf = 0; nf < 8; nf++) {
            int col = nf * 8 + 2 * t;
            float2 v0; v0.x = of[nf][0] * il0; v0.y = of[nf][1] * il0;
            float2 v1; v1.x = of[nf][2] * il1; v1.y = of[nf][3] * il1;
            *reinterpret_cast<float2*>(&g_ab[(((size_t)b * SEQ + sq0) * HEADS + h) * HD + col]) = v0;
            *reinterpret_cast<float2*>(&g_ab[(((size_t)b * SEQ + sq1) * HEADS + h) * HD + col]) = v1;
        }
    }
}

// ---------------- launch ----------------
extern "C" void kernel_launch(void* const* d_in, const int* in_sizes, int n_in,
                              void* d_out, int out_size)
{
    const float* x    = (const float*)d_in[0];
    const float* Wqkv = (const float*)d_in[1];
    const float* bqkv = (const float*)d_in[2];
    const float* Wd   = (const float*)d_in[3];
    const float* bd   = (const float*)d_in[4];
    const int*   mask = (const int*)d_in[5];
    float* out = (float*)d_out;

    cudaFuncSetAttribute(gemm_kernel<0>, cudaFuncAttributeMaxDynamicSharedMemorySize, GEMM_SMEM_BYTES);
    cudaFuncSetAttribute(gemm_kernel<1>, cudaFuncAttributeMaxDynamicSharedMemorySize, GEMM_SMEM_BYTES);
    cudaFuncSetAttribute(fa_kernel,      cudaFuncAttributeMaxDynamicSharedMemorySize, FA_SMEM_BYTES);

    gemm_kernel<0><<<dim3(N_QKV / 128, MTOT / 128), 256, GEMM_SMEM_BYTES>>>(
        x, Wqkv, bqkv, nullptr, MTOT, N_QKV, DMODEL);

    fa_kernel<<<dim3(16, NB * HEADS), 128, FA_SMEM_BYTES>>>(mask);

    gemm_kernel<1><<<dim3(DMODEL / 128, MTOT / 128), 256, GEMM_SMEM_BYTES>>>(
        nullptr, Wd, bd, out, MTOT, DMODEL, DMODEL);
}

// round 10
// speedup vs baseline: 1.8759x; 1.4604x over previous
#include <cuda_runtime.h>
#include <cstdint>

#define NB      2
#define SEQ     2048
#define DMODEL  1024
#define HEADS   16
#define HD      64
#define MTOT    (NB*SEQ)        // 4096
#define N_QKV   (3*DMODEL)      // 3072

// Scratch (static device globals -- no allocation anywhere)
__device__ float g_qb[NB*HEADS*SEQ*HD];   // [b,h,s,hd]  (tf32-rounded)
__device__ float g_kb[NB*HEADS*SEQ*HD];
__device__ float g_vb[NB*HEADS*SEQ*HD];
__device__ float g_ab[MTOT*DMODEL];       // attention out (tf32-rounded)
__device__ float g_xr[MTOT*DMODEL];       // tf32-rounded x
__device__ float g_wqr[N_QKV*DMODEL];     // tf32-rounded Wqkv
__device__ float g_wdr[DMODEL*DMODEL];    // tf32-rounded Wd

// ---------------- helpers ----------------
__device__ __forceinline__ unsigned f2tf(float x) {
    unsigned u; asm("cvt.rna.tf32.f32 %0, %1;" : "=r"(u) : "f"(x)); return u;
}
__device__ __forceinline__ float f2tff(float x) { return __uint_as_float(f2tf(x)); }

__device__ __forceinline__ void mma8(float c[4],
                                     unsigned a0, unsigned a1, unsigned a2, unsigned a3,
                                     unsigned b0, unsigned b1) {
    asm volatile(
        "mma.sync.aligned.m16n8k8.row.col.f32.tf32.tf32.f32 "
        "{%0,%1,%2,%3}, {%4,%5,%6,%7}, {%8,%9}, {%0,%1,%2,%3};\n"
        : "+f"(c[0]), "+f"(c[1]), "+f"(c[2]), "+f"(c[3])
        : "r"(a0), "r"(a1), "r"(a2), "r"(a3), "r"(b0), "r"(b1));
}

__device__ __forceinline__ uint32_t s2u(const void* p) {
    uint32_t a;
    asm("{ .reg .u64 t; cvta.to.shared.u64 t, %1; cvt.u32.u64 %0, t; }"
        : "=r"(a) : "l"(p));
    return a;
}

__device__ __forceinline__ void cpasync16(uint32_t s, const void* g) {
    asm volatile("cp.async.cg.shared.global [%0], [%1], 16;" :: "r"(s), "l"(g));
}
__device__ __forceinline__ void cpcommit() {
    asm volatile("cp.async.commit_group;" ::: "memory");
}
__device__ __forceinline__ void cpwait0() {
    asm volatile("cp.async.wait_group 0;" ::: "memory");
}
__device__ __forceinline__ void cpwait1() {
    asm volatile("cp.async.wait_group 1;" ::: "memory");
}

// ---------------- pre-round: rna-round x, Wqkv, Wd to tf32-in-fp32 ----------------
__global__ void round_kernel(const float* __restrict__ x,
                             const float* __restrict__ wqkv,
                             const float* __restrict__ wd)
{
    const int N1 = MTOT * DMODEL / 4;
    const int N2 = N_QKV * DMODEL / 4;
    const int N3 = DMODEL * DMODEL / 4;
    const int total = N1 + N2 + N3;
    for (int i = blockIdx.x * blockDim.x + threadIdx.x; i < total;
         i += gridDim.x * blockDim.x) {
        const float4* src; float4* dst; int off;
        if (i < N1)           { src = (const float4*)x;    dst = (float4*)g_xr;  off = i; }
        else if (i < N1 + N2) { src = (const float4*)wqkv; dst = (float4*)g_wqr; off = i - N1; }
        else                  { src = (const float4*)wd;   dst = (float4*)g_wdr; off = i - N1 - N2; }
        float4 v = src[off];
        v.x = f2tff(v.x); v.y = f2tff(v.y); v.z = f2tff(v.z); v.w = f2tff(v.w);
        dst[off] = v;
    }
}

// ---------------- GEMM: C[M,N] = A[M,K] @ B[N,K]^T + bias ----------------
// Inputs pre-rounded -> staging is a raw cp.async copy, 2-stage pipeline.
// R0 fragment pattern (32-bit, stride-36, conflict-free).
// __launch_bounds__(256,2) pins regs <= 128 so 2 CTAs/SM stay resident.
#define GEMM_SMEM_BYTES (2 * 2 * 128 * 36 * 4)   // 73728: 2 stages x (A+B)

template<int MODE>
__global__ __launch_bounds__(256, 2)
void gemm_kernel(const float* __restrict__ Bw, const float* __restrict__ bias,
                 float* __restrict__ C, int M, int N, int K)
{
    extern __shared__ float gsm[];
    const float* A = (MODE == 1) ? g_ab : g_xr;
    const float* B = Bw;

    const uint32_t sbase = s2u(gsm);
    const int tid  = threadIdx.x;
    const int wid  = tid >> 5, lane = tid & 31;
    const int g    = lane >> 2, t = lane & 3;
    const int wm   = (wid >> 2) * 64;   // 2 warps in m
    const int wn   = (wid & 3) * 32;    // 4 warps in n
    const int m0   = blockIdx.y * 128, n0 = blockIdx.x * 128;

    // staging indices: 4 float4 of A + 4 of B per thread per chunk
    int srow[4], scol[4];
#pragma unroll
    for (int i = 0; i < 4; i++) {
        int lin = tid + i * 256;
        srow[i] = lin >> 3;
        scol[i] = (lin & 7) << 2;
    }

    float acc[4][4][4];
#pragma unroll
    for (int i = 0; i < 4; i++)
#pragma unroll
        for (int j = 0; j < 4; j++)
#pragma unroll
            for (int c = 0; c < 4; c++) acc[i][j][c] = 0.f;

    // stage st: A at floats st*9216, B at st*9216+4608
    // issue chunk 0 into stage 0
#pragma unroll
    for (int i = 0; i < 4; i++) {
        uint32_t so = (uint32_t)(srow[i] * 36 + scol[i]) * 4;
        cpasync16(sbase + so,            &A[(size_t)(m0 + srow[i]) * K + scol[i]]);
        cpasync16(sbase + 18432u + so,   &B[(size_t)(n0 + srow[i]) * K + scol[i]]);
    }
    cpcommit();

    const int NCH = K / 32;
    for (int ch = 0; ch < NCH; ch++) {
        const int cur = ch & 1;
        if (ch + 1 < NCH) {
            const int nxt = cur ^ 1;
            const int kn = (ch + 1) * 32;
#pragma unroll
            for (int i = 0; i < 4; i++) {
                uint32_t so = (uint32_t)(nxt * 36864) + (uint32_t)(srow[i] * 36 + scol[i]) * 4;
                cpasync16(sbase + so,          &A[(size_t)(m0 + srow[i]) * K + kn + scol[i]]);
                cpasync16(sbase + 18432u + so, &B[(size_t)(n0 + srow[i]) * K + kn + scol[i]]);
            }
            cpcommit();
            cpwait1();          // chunk ch ready; chunk ch+1 still in flight
        } else {
            cpwait0();
        }
        __syncthreads();

        const float* As = gsm + cur * 9216;
        const float* Bs = As + 4608;
#pragma unroll
        for (int kk = 0; kk < 4; kk++) {
            unsigned a[4][4], b[4][2];
#pragma unroll
            for (int mf = 0; mf < 4; mf++) {
                int rb = wm + mf * 16;
                a[mf][0] = __float_as_uint(As[(rb + g    ) * 36 + kk * 8 + t    ]);
                a[mf][1] = __float_as_uint(As[(rb + g + 8) * 36 + kk * 8 + t    ]);
                a[mf][2] = __float_as_uint(As[(rb + g    ) * 36 + kk * 8 + t + 4]);
                a[mf][3] = __float_as_uint(As[(rb + g + 8) * 36 + kk * 8 + t + 4]);
            }
#pragma unroll
            for (int nf = 0; nf < 4; nf++) {
                int nb = wn + nf * 8;
                b[nf][0] = __float_as_uint(Bs[(nb + g) * 36 + kk * 8 + t    ]);
                b[nf][1] = __float_as_uint(Bs[(nb + g) * 36 + kk * 8 + t + 4]);
            }
#pragma unroll
            for (int mf = 0; mf < 4; mf++)
#pragma unroll
                for (int nf = 0; nf < 4; nf++)
                    mma8(acc[mf][nf], a[mf][0], a[mf][1], a[mf][2], a[mf][3],
                         b[nf][0], b[nf][1]);
        }
        __syncthreads();   // done reading cur before next iter's issue overwrites it
    }

#pragma unroll
    for (int mf = 0; mf < 4; mf++)
#pragma unroll
        for (int nf = 0; nf < 4; nf++)
#pragma unroll
            for (int c = 0; c < 4; c++) {
                int row = m0 + wm + mf * 16 + g + ((c >= 2) ? 8 : 0);
                int col = n0 + wn + nf * 8 + 2 * t + (c & 1);
                float v = acc[mf][nf][c] + bias[col];
                if (MODE == 0) {
                    int part = col >> 10, nn = col & 1023;
                    int hh = nn >> 6, e = nn & 63;
                    int bb = row >> 11, sq = row & 2047;
                    float* dst = (part == 0) ? g_qb : ((part == 1) ? g_kb : g_vb);
                    // round here: fa consumes raw
                    dst[(((size_t)(bb * HEADS + hh)) * SEQ + sq) * HD + e] = f2tff(v);
                } else {
                    C[(size_t)row * N + col] = v;   // final output: no rounding
                }
            }
}

// ---------------- Flash attention ----------------
// 128 threads (4 warps). CTA x=p handles q-tiles {p, 31-p} (balanced causal).
// K/V double-buffered via cp.async (raw copies; data pre-rounded). Register
// softmax; P in its own buffer, rounded at store. 2 barriers/iter.
#define FA_SMEM_BYTES (5 * 64 * 68 * 4)   // 87040: K0,K1,V0,V1,P

__global__ __launch_bounds__(128)
void fa_kernel(const int* __restrict__ maskp)
{
    extern __shared__ float fsm[];
    // float offsets: K stage s: s*4352 ; V stage s: 8704 + s*4352 ; P: 17408
    float* Ps = fsm + 17408;

    const int tid = threadIdx.x, wid = tid >> 5, lane = tid & 31;
    const int g = lane >> 2, t = lane & 3;
    const int bh = blockIdx.y;
    const int causal = (maskp[0] != 0);

    const float* kp = g_kb + (size_t)bh * SEQ * HD;
    const float* vp = g_vb + (size_t)bh * SEQ * HD;
    const uint32_t fbase = s2u(fsm);
    const int wr = wid * 16;
    const int row0 = wr + g, row1 = wr + g + 8;   // tile-local rows
    const int b = bh >> 4, h = bh & 15;

    // per-thread staging indices: 8 float4 per tile
    int krow[8], kc4[8];
#pragma unroll
    for (int i = 0; i < 8; i++) {
        int lin = tid + i * 128;
        krow[i] = lin >> 4;
        kc4[i]  = (lin & 15) << 2;
    }

    for (int sub = 0; sub < 2; sub++) {
        const int qi = sub ? (31 - (int)blockIdx.x) : (int)blockIdx.x;
        const float* qp = g_qb + ((size_t)bh * SEQ + qi * 64) * HD;

        // Q fragments (pre-rounded -> raw loads)
        unsigned qf[8][4];
#pragma unroll
        for (int kk = 0; kk < 8; kk++) {
            qf[kk][0] = __float_as_uint(qp[(wr + g    ) * HD + kk * 8 + t    ]);
            qf[kk][1] = __float_as_uint(qp[(wr + g + 8) * HD + kk * 8 + t    ]);
            qf[kk][2] = __float_as_uint(qp[(wr + g    ) * HD + kk * 8 + t + 4]);
            qf[kk][3] = __float_as_uint(qp[(wr + g + 8) * HD + kk * 8 + t + 4]);
        }

        float of[8][4];
#pragma unroll
        for (int nf = 0; nf < 8; nf++)
#pragma unroll
            for (int c = 0; c < 4; c++) of[nf][c] = 0.f;

        float m0 = -1e30f, m1 = -1e30f, l0 = 0.f, l1 = 0.f;

        const int jend = causal ? (qi + 1) : (SEQ / 64);

        // prologue: issue K/V for j=0 into stage 0
#pragma unroll
        for (int i = 0; i < 8; i++) {
            uint32_t so = (uint32_t)(krow[i] * 68 + kc4[i]) * 4;
            cpasync16(fbase + so,           &kp[(size_t)krow[i] * HD + kc4[i]]);
            cpasync16(fbase + 34816u + so,  &vp[(size_t)krow[i] * HD + kc4[i]]);
        }
        cpcommit();

        for (int j = 0; j < jend; j++) {
            const int cur = j & 1;
            if (j + 1 < jend) {
                const int nxt = cur ^ 1;
#pragma unroll
                for (int i = 0; i < 8; i++) {
                    uint32_t so = (uint32_t)(nxt * 17408) + (uint32_t)(krow[i] * 68 + kc4[i]) * 4;
                    cpasync16(fbase + so,          &kp[((size_t)(j + 1) * 64 + krow[i]) * HD + kc4[i]]);
                    cpasync16(fbase + 34816u + so, &vp[((size_t)(j + 1) * 64 + krow[i]) * HD + kc4[i]]);
                }
                cpcommit();
                cpwait1();
            } else {
                cpwait0();
            }
            __syncthreads();

            const float* Ks = fsm + cur * 4352;
            const float* Vs = fsm + 8704 + cur * 4352;

            // S = Q K^T
            float sf[8][4];
#pragma unroll
            for (int nf = 0; nf < 8; nf++)
#pragma unroll
                for (int c = 0; c < 4; c++) sf[nf][c] = 0.f;
#pragma unroll
            for (int kk = 0; kk < 8; kk++) {
#pragma unroll
                for (int nf = 0; nf < 8; nf++) {
                    unsigned b0 = __float_as_uint(Ks[(nf * 8 + g) * 68 + kk * 8 + t    ]);
                    unsigned b1 = __float_as_uint(Ks[(nf * 8 + g) * 68 + kk * 8 + t + 4]);
                    mma8(sf[nf], qf[kk][0], qf[kk][1], qf[kk][2], qf[kk][3], b0, b1);
                }
            }

            // scale + causal mask in registers
            const bool mk = causal && (j == qi);
#pragma unroll
            for (int nf = 0; nf < 8; nf++) {
                int c0 = nf * 8 + 2 * t, c1 = c0 + 1;
                sf[nf][0] = (mk && c0 > row0) ? -1e30f : sf[nf][0] * 0.125f;
                sf[nf][1] = (mk && c1 > row0) ? -1e30f : sf[nf][1] * 0.125f;
                sf[nf][2] = (mk && c0 > row1) ? -1e30f : sf[nf][2] * 0.125f;
                sf[nf][3] = (mk && c1 > row1) ? -1e30f : sf[nf][3] * 0.125f;
            }

            // register softmax: row reduction across the t-quad
            float mx0 = -1e30f, mx1 = -1e30f;
#pragma unroll
            for (int nf = 0; nf < 8; nf++) {
                mx0 = fmaxf(mx0, fmaxf(sf[nf][0], sf[nf][1]));
                mx1 = fmaxf(mx1, fmaxf(sf[nf][2], sf[nf][3]));
            }
            mx0 = fmaxf(mx0, __shfl_xor_sync(0xffffffffu, mx0, 1));
            mx0 = fmaxf(mx0, __shfl_xor_sync(0xffffffffu, mx0, 2));
            mx1 = fmaxf(mx1, __shfl_xor_sync(0xffffffffu, mx1, 1));
            mx1 = fmaxf(mx1, __shfl_xor_sync(0xffffffffu, mx1, 2));
            const float nm0 = fmaxf(m0, mx0), nm1 = fmaxf(m1, mx1);

            float sum0 = 0.f, sum1 = 0.f;
#pragma unroll
            for (int nf = 0; nf < 8; nf++) {
                sf[nf][0] = __expf(sf[nf][0] - nm0);
                sf[nf][1] = __expf(sf[nf][1] - nm0);
                sf[nf][2] = __expf(sf[nf][2] - nm1);
                sf[nf][3] = __expf(sf[nf][3] - nm1);
                sum0 += sf[nf][0] + sf[nf][1];
                sum1 += sf[nf][2] + sf[nf][3];
            }
            sum0 += __shfl_xor_sync(0xffffffffu, sum0, 1);
            sum0 += __shfl_xor_sync(0xffffffffu, sum0, 2);
            sum1 += __shfl_xor_sync(0xffffffffu, sum1, 1);
            sum1 += __shfl_xor_sync(0xffffffffu, sum1, 2);

            const float sc0 = __expf(m0 - nm0), sc1 = __expf(m1 - nm1);
            l0 = l0 * sc0 + sum0; l1 = l1 * sc1 + sum1;
            m0 = nm0; m1 = nm1;

            // P (rounded at store) to its own buffer: no hazard with K reads
#pragma unroll
            for (int nf = 0; nf < 8; nf++) {
                int c0 = nf * 8 + 2 * t;
                Ps[row0 * 68 + c0    ] = f2tff(sf[nf][0]);
                Ps[row0 * 68 + c0 + 1] = f2tff(sf[nf][1]);
                Ps[row1 * 68 + c0    ] = f2tff(sf[nf][2]);
                Ps[row1 * 68 + c0 + 1] = f2tff(sf[nf][3]);
            }
            __syncwarp();   // PV A-fragments read only this warp's 16 rows

            // rescale O, then O += P V
#pragma unroll
            for (int nf = 0; nf < 8; nf++) {
                of[nf][0] *= sc0; of[nf][1] *= sc0; of[nf][2] *= sc1; of[nf][3] *= sc1;
            }
#pragma unroll
            for (int kk = 0; kk < 8; kk++) {
                unsigned a0 = __float_as_uint(Ps[(wr + g    ) * 68 + kk * 8 + t    ]);
                unsigned a1 = __float_as_uint(Ps[(wr + g + 8) * 68 + kk * 8 + t    ]);
                unsigned a2 = __float_as_uint(Ps[(wr + g    ) * 68 + kk * 8 + t + 4]);
                unsigned a3 = __float_as_uint(Ps[(wr + g + 8) * 68 + kk * 8 + t + 4]);
#pragma unroll
                for (int nf = 0; nf < 8; nf++) {
                    unsigned b0 = __float_as_uint(Vs[(kk * 8 + t    ) * 68 + nf * 8 + g]);
                    unsigned b1 = __float_as_uint(Vs[(kk * 8 + t + 4) * 68 + nf * 8 + g]);
                    mma8(of[nf], a0, a1, a2, a3, b0, b1);
                }
            }
            __syncthreads();   // done with Ks/Vs before next issue overwrites
        }

        // normalize and write (rounded: gemm<1> consumes raw)
        const float il0 = 1.f / l0, il1 = 1.f / l1;
        const int sq0 = qi * 64 + row0, sq1 = qi * 64 + row1;
#pragma unroll
        for (int nf = 0; nf < 8; nf++) {
            int col = nf * 8 + 2 * t;
            float2 v0; v0.x = f2tff(of[nf][0] * il0); v0.y = f2tff(of[nf][1] * il0);
            float2 v1; v1.x = f2tff(of[nf][2] * il1); v1.y = f2tff(of[nf][3] * il1);
            *reinterpret_cast<float2*>(&g_ab[(((size_t)b * SEQ + sq0) * HEADS + h) * HD + col]) = v0;
            *reinterpret_cast<float2*>(&g_ab[(((size_t)b * SEQ + sq1) * HEADS + h) * HD + col]) = v1;
        }
    }
}

// ---------------- launch ----------------
extern "C" void kernel_launch(void* const* d_in, const int* in_sizes, int n_in,
                              void* d_out, int out_size)
{
    const float* x    = (const float*)d_in[0];
    const float* Wqkv = (const float*)d_in[1];
    const float* bqkv = (const float*)d_in[2];
    const float* Wd   = (const float*)d_in[3];
    const float* bd   = (const float*)d_in[4];
    const int*   mask = (const int*)d_in[5];
    float* out = (float*)d_out;

    cudaFuncSetAttribute(gemm_kernel<0>, cudaFuncAttributeMaxDynamicSharedMemorySize, GEMM_SMEM_BYTES);
    cudaFuncSetAttribute(gemm_kernel<1>, cudaFuncAttributeMaxDynamicSharedMemorySize, GEMM_SMEM_BYTES);
    cudaFuncSetAttribute(fa_kernel,      cudaFuncAttributeMaxDynamicSharedMemorySize, FA_SMEM_BYTES);

    // fetch device-global weight pointers is not needed: kernels reference them directly
    round_kernel<<<1024, 256>>>(x, Wqkv, Wd);

    // B pointer passed via device-global bridge kernels would be cleaner, but
    // gemm reads its own A; B we pass by reading the rounded globals through a
    // device pointer obtained inside the kernel via the template MODE:
    // MODE 0 -> g_wqr, MODE 1 -> g_wdr (selected below by passing nullptr? no):
    // we simply pass the rounded-global addresses through kernel args using
    // device-symbol lookup-free trick: a tiny dispatch kernel is overkill, so
    // gemm dereferences Bw; we get the addresses with cudaGetSymbolAddress.
    static float* wq_dev = nullptr;
    static float* wd_dev = nullptr;
    if (!wq_dev) {
        cudaGetSymbolAddress((void**)&wq_dev, g_wqr);
        cudaGetSymbolAddress((void**)&wd_dev, g_wdr);
    }

    gemm_kernel<0><<<dim3(N_QKV / 128, MTOT / 128), 256, GEMM_SMEM_BYTES>>>(
        wq_dev, bqkv, nullptr, MTOT, N_QKV, DMODEL);

    fa_kernel<<<dim3(16, NB * HEADS), 128, FA_SMEM_BYTES>>>(mask);

    gemm_kernel<1><<<dim3(DMODEL / 128, MTOT / 128), 256, GEMM_SMEM_BYTES>>>(
        wd_dev, bd, out, MTOT, DMODEL, DMODEL);
}

// round 11
// speedup vs baseline: 2.0520x; 1.0939x over previous
#include <cuda_runtime.h>
#include <cstdint>

#define NB      2
#define SEQ     2048
#define DMODEL  1024
#define HEADS   16
#define HD      64
#define MTOT    (NB*SEQ)        // 4096
#define N_QKV   (3*DMODEL)      // 3072

// Scratch (static device globals -- no allocation anywhere)
__device__ float g_qb[NB*HEADS*SEQ*HD];   // [b,h,s,hd]  (tf32-rounded)
__device__ float g_kb[NB*HEADS*SEQ*HD];
__device__ float g_vb[NB*HEADS*SEQ*HD];
__device__ float g_ab[MTOT*DMODEL];       // attention out (tf32-rounded)
__device__ float g_xr[MTOT*DMODEL];       // tf32-rounded x
__device__ float g_wqr[N_QKV*DMODEL];     // tf32-rounded Wqkv
__device__ float g_wdr[DMODEL*DMODEL];    // tf32-rounded Wd

// ---------------- helpers ----------------
__device__ __forceinline__ unsigned f2tf(float x) {
    unsigned u; asm("cvt.rna.tf32.f32 %0, %1;" : "=r"(u) : "f"(x)); return u;
}
__device__ __forceinline__ float f2tff(float x) { return __uint_as_float(f2tf(x)); }

__device__ __forceinline__ void mma8(float c[4],
                                     unsigned a0, unsigned a1, unsigned a2, unsigned a3,
                                     unsigned b0, unsigned b1) {
    asm volatile(
        "mma.sync.aligned.m16n8k8.row.col.f32.tf32.tf32.f32 "
        "{%0,%1,%2,%3}, {%4,%5,%6,%7}, {%8,%9}, {%0,%1,%2,%3};\n"
        : "+f"(c[0]), "+f"(c[1]), "+f"(c[2]), "+f"(c[3])
        : "r"(a0), "r"(a1), "r"(a2), "r"(a3), "r"(b0), "r"(b1));
}

__device__ __forceinline__ uint32_t s2u(const void* p) {
    uint32_t a;
    asm("{ .reg .u64 t; cvta.to.shared.u64 t, %1; cvt.u32.u64 %0, t; }"
        : "=r"(a) : "l"(p));
    return a;
}

__device__ __forceinline__ void cpasync16(uint32_t s, const void* g) {
    asm volatile("cp.async.cg.shared.global [%0], [%1], 16;" :: "r"(s), "l"(g));
}
__device__ __forceinline__ void cpcommit() {
    asm volatile("cp.async.commit_group;" ::: "memory");
}
__device__ __forceinline__ void cpwait0() {
    asm volatile("cp.async.wait_group 0;" ::: "memory");
}
__device__ __forceinline__ void cpwait1() {
    asm volatile("cp.async.wait_group 1;" ::: "memory");
}

// ---------------- pre-round: rna-round x, Wqkv, Wd to tf32-in-fp32 ----------------
__global__ void round_kernel(const float* __restrict__ x,
                             const float* __restrict__ wqkv,
                             const float* __restrict__ wd)
{
    const int N1 = MTOT * DMODEL / 4;
    const int N2 = N_QKV * DMODEL / 4;
    const int N3 = DMODEL * DMODEL / 4;
    const int total = N1 + N2 + N3;
    for (int i = blockIdx.x * blockDim.x + threadIdx.x; i < total;
         i += gridDim.x * blockDim.x) {
        const float4* src; float4* dst; int off;
        if (i < N1)           { src = (const float4*)x;    dst = (float4*)g_xr;  off = i; }
        else if (i < N1 + N2) { src = (const float4*)wqkv; dst = (float4*)g_wqr; off = i - N1; }
        else                  { src = (const float4*)wd;   dst = (float4*)g_wdr; off = i - N1 - N2; }
        float4 v = src[off];
        v.x = f2tff(v.x); v.y = f2tff(v.y); v.z = f2tff(v.z); v.w = f2tff(v.w);
        dst[off] = v;
    }
}

// ---------------- GEMM: C[M,N] = A[M,K] @ B[N,K]^T + bias ----------------
// Pre-rounded inputs; cp.async 2-stage pipeline; stride-40 smem rows so the
// k-permuted fragments load as conflict-free LDS.64 (pair idx (20r+t)%16 ->
// 4g+t distinct per half-warp). k-slot permutation: slot t <-> col 2t,
// slot t+4 <-> col 2t+1 (A and B agree; C layout is unaffected).
#define GEMM_SMEM_BYTES (2 * 2 * 128 * 40 * 4)   // 81920: 2 stages x (A+B) x 128x40

template<int MODE>
__global__ __launch_bounds__(256, 2)
void gemm_kernel(const float* __restrict__ Bw, const float* __restrict__ bias,
                 float* __restrict__ C, int M, int N, int K)
{
    extern __shared__ float gsm[];
    const float* A = (MODE == 1) ? g_ab : g_xr;
    const float* B = Bw;

    const uint32_t sbase = s2u(gsm);
    const int tid  = threadIdx.x;
    const int wid  = tid >> 5, lane = tid & 31;
    const int g    = lane >> 2, t = lane & 3;
    const int wm   = (wid >> 2) * 64;   // 2 warps in m
    const int wn   = (wid & 3) * 32;    // 4 warps in n
    const int m0   = blockIdx.y * 128, n0 = blockIdx.x * 128;

    int srow[4], scol[4];
#pragma unroll
    for (int i = 0; i < 4; i++) {
        int lin = tid + i * 256;
        srow[i] = lin >> 3;
        scol[i] = (lin & 7) << 2;
    }

    float acc[4][4][4];
#pragma unroll
    for (int i = 0; i < 4; i++)
#pragma unroll
        for (int j = 0; j < 4; j++)
#pragma unroll
            for (int c = 0; c < 4; c++) acc[i][j][c] = 0.f;

    // stage s (bytes): A at s*40960, B at s*40960 + 20480
#pragma unroll
    for (int i = 0; i < 4; i++) {
        uint32_t so = (uint32_t)(srow[i] * 40 + scol[i]) * 4;
        cpasync16(sbase + so,          &A[(size_t)(m0 + srow[i]) * K + scol[i]]);
        cpasync16(sbase + 20480u + so, &B[(size_t)(n0 + srow[i]) * K + scol[i]]);
    }
    cpcommit();

    const int NCH = K / 32;
    for (int ch = 0; ch < NCH; ch++) {
        const int cur = ch & 1;
        if (ch + 1 < NCH) {
            const int nxt = cur ^ 1;
            const int kn = (ch + 1) * 32;
#pragma unroll
            for (int i = 0; i < 4; i++) {
                uint32_t so = (uint32_t)(nxt * 40960) + (uint32_t)(srow[i] * 40 + scol[i]) * 4;
                cpasync16(sbase + so,          &A[(size_t)(m0 + srow[i]) * K + kn + scol[i]]);
                cpasync16(sbase + 20480u + so, &B[(size_t)(n0 + srow[i]) * K + kn + scol[i]]);
            }
            cpcommit();
            cpwait1();
        } else {
            cpwait0();
        }
        __syncthreads();

        const float* As = gsm + cur * 10240;
        const float* Bs = As + 5120;
#pragma unroll
        for (int kk = 0; kk < 4; kk++) {
            unsigned a[4][4], b[4][2];
#pragma unroll
            for (int mf = 0; mf < 4; mf++) {
                int rb = wm + mf * 16;
                float2 a0 = *reinterpret_cast<const float2*>(&As[(rb + g    ) * 40 + kk * 8 + 2 * t]);
                float2 a1 = *reinterpret_cast<const float2*>(&As[(rb + g + 8) * 40 + kk * 8 + 2 * t]);
                a[mf][0] = __float_as_uint(a0.x);
                a[mf][1] = __float_as_uint(a1.x);
                a[mf][2] = __float_as_uint(a0.y);
                a[mf][3] = __float_as_uint(a1.y);
            }
#pragma unroll
            for (int nf = 0; nf < 4; nf++) {
                int nb = wn + nf * 8;
                float2 bv = *reinterpret_cast<const float2*>(&Bs[(nb + g) * 40 + kk * 8 + 2 * t]);
                b[nf][0] = __float_as_uint(bv.x);
                b[nf][1] = __float_as_uint(bv.y);
            }
#pragma unroll
            for (int mf = 0; mf < 4; mf++)
#pragma unroll
                for (int nf = 0; nf < 4; nf++)
                    mma8(acc[mf][nf], a[mf][0], a[mf][1], a[mf][2], a[mf][3],
                         b[nf][0], b[nf][1]);
        }
        __syncthreads();
    }

#pragma unroll
    for (int mf = 0; mf < 4; mf++)
#pragma unroll
        for (int nf = 0; nf < 4; nf++)
#pragma unroll
            for (int c = 0; c < 4; c++) {
                int row = m0 + wm + mf * 16 + g + ((c >= 2) ? 8 : 0);
                int col = n0 + wn + nf * 8 + 2 * t + (c & 1);
                float v = acc[mf][nf][c] + bias[col];
                if (MODE == 0) {
                    int part = col >> 10, nn = col & 1023;
                    int hh = nn >> 6, e = nn & 63;
                    int bb = row >> 11, sq = row & 2047;
                    float* dst = (part == 0) ? g_qb : ((part == 1) ? g_kb : g_vb);
                    dst[(((size_t)(bb * HEADS + hh)) * SEQ + sq) * HD + e] = f2tff(v);
                } else {
                    C[(size_t)row * N + col] = v;
                }
            }
}

// ---------------- Flash attention ----------------
// 256 threads (8 warps), 128-row q tile (16 tiles). CTA x=p handles tiles
// {p, 15-p}: causal work is a uniform 34 kv-iterations per CTA.
// K/V double-buffered cp.async, stride 72 (conflict-free LDS.64 for the
// permuted S-mma K fragments). PV path standard (R9-proven). P separate.
#define FA_SMEM_BYTES ((2*64*72 + 2*64*72 + 128*68) * 4)   // 108544

__global__ __launch_bounds__(256)
void fa_kernel(const int* __restrict__ maskp)
{
    extern __shared__ float fsm[];
    // float offsets: K stage s: s*4608; V stage s: 9216 + s*4608; P: 18432
    float* Ps = fsm + 18432;

    const int tid = threadIdx.x, wid = tid >> 5, lane = tid & 31;
    const int g = lane >> 2, t = lane & 3;
    const int bh = blockIdx.y;
    const int causal = (maskp[0] != 0);

    const float* kp = g_kb + (size_t)bh * SEQ * HD;
    const float* vp = g_vb + (size_t)bh * SEQ * HD;
    const uint32_t fbase = s2u(fsm);
    const int wr = wid * 16;
    const int row0 = wr + g, row1 = wr + g + 8;   // q-tile-local rows (0..127)
    const int b = bh >> 4, h = bh & 15;

    // staging: 64 rows x 16 float4; 256 threads -> 4 each
    int krow[4], kc4[4];
#pragma unroll
    for (int i = 0; i < 4; i++) {
        int lin = tid + i * 256;
        krow[i] = lin >> 4;
        kc4[i]  = (lin & 15) << 2;
    }

    for (int sub = 0; sub < 2; sub++) {
        const int Q = sub ? (15 - (int)blockIdx.x) : (int)blockIdx.x;
        const float* qp = g_qb + ((size_t)bh * SEQ + Q * 128) * HD;

        // Q fragments, k-permuted (slot t <-> col 2t): float2 global loads
        unsigned qf[8][4];
#pragma unroll
        for (int kk = 0; kk < 8; kk++) {
            float2 x0 = *reinterpret_cast<const float2*>(&qp[(size_t)row0 * HD + kk * 8 + 2 * t]);
            float2 x1 = *reinterpret_cast<const float2*>(&qp[(size_t)row1 * HD + kk * 8 + 2 * t]);
            qf[kk][0] = __float_as_uint(x0.x);
            qf[kk][1] = __float_as_uint(x1.x);
            qf[kk][2] = __float_as_uint(x0.y);
            qf[kk][3] = __float_as_uint(x1.y);
        }

        float of[8][4];
#pragma unroll
        for (int nf = 0; nf < 8; nf++)
#pragma unroll
            for (int c = 0; c < 4; c++) of[nf][c] = 0.f;

        float m0 = -1e30f, m1 = -1e30f, l0 = 0.f, l1 = 0.f;
        const int grow0 = Q * 128 + row0, grow1 = Q * 128 + row1;

        const int jend = causal ? (2 * Q + 2) : (SEQ / 64);

        // prologue: issue K/V for j=0 into stage 0
#pragma unroll
        for (int i = 0; i < 4; i++) {
            uint32_t so = (uint32_t)(krow[i] * 72 + kc4[i]) * 4;
            cpasync16(fbase + so,           &kp[(size_t)krow[i] * HD + kc4[i]]);
            cpasync16(fbase + 36864u + so,  &vp[(size_t)krow[i] * HD + kc4[i]]);
        }
        cpcommit();

        for (int j = 0; j < jend; j++) {
            const int cur = j & 1;
            if (j + 1 < jend) {
                const int nxt = cur ^ 1;
#pragma unroll
                for (int i = 0; i < 4; i++) {
                    uint32_t so = (uint32_t)(nxt * 18432) + (uint32_t)(krow[i] * 72 + kc4[i]) * 4;
                    cpasync16(fbase + so,          &kp[((size_t)(j + 1) * 64 + krow[i]) * HD + kc4[i]]);
                    cpasync16(fbase + 36864u + so, &vp[((size_t)(j + 1) * 64 + krow[i]) * HD + kc4[i]]);
                }
                cpcommit();
                cpwait1();
            } else {
                cpwait0();
            }
            __syncthreads();

            const float* Ks = fsm + cur * 4608;
            const float* Vs = fsm + 9216 + cur * 4608;

            // S = Q K^T  (k-permuted: B fragments are LDS.64, conflict-free)
            float sf[8][4];
#pragma unroll
            for (int nf = 0; nf < 8; nf++)
#pragma unroll
                for (int c = 0; c < 4; c++) sf[nf][c] = 0.f;
#pragma unroll
            for (int kk = 0; kk < 8; kk++) {
#pragma unroll
                for (int nf = 0; nf < 8; nf++) {
                    float2 bv = *reinterpret_cast<const float2*>(&Ks[(nf * 8 + g) * 72 + kk * 8 + 2 * t]);
                    mma8(sf[nf], qf[kk][0], qf[kk][1], qf[kk][2], qf[kk][3],
                         __float_as_uint(bv.x), __float_as_uint(bv.y));
                }
            }

            // scale + causal mask (global indices; only j >= 2Q tiles cross)
            const bool mk = causal && (j >= 2 * Q);
            const int jc = j * 64;
#pragma unroll
            for (int nf = 0; nf < 8; nf++) {
                int c0 = jc + nf * 8 + 2 * t, c1 = c0 + 1;
                sf[nf][0] = (mk && c0 > grow0) ? -1e30f : sf[nf][0] * 0.125f;
                sf[nf][1] = (mk && c1 > grow0) ? -1e30f : sf[nf][1] * 0.125f;
                sf[nf][2] = (mk && c0 > grow1) ? -1e30f : sf[nf][2] * 0.125f;
                sf[nf][3] = (mk && c1 > grow1) ? -1e30f : sf[nf][3] * 0.125f;
            }

            // register softmax: row reduction across the t-quad
            float mx0 = -1e30f, mx1 = -1e30f;
#pragma unroll
            for (int nf = 0; nf < 8; nf++) {
                mx0 = fmaxf(mx0, fmaxf(sf[nf][0], sf[nf][1]));
                mx1 = fmaxf(mx1, fmaxf(sf[nf][2], sf[nf][3]));
            }
            mx0 = fmaxf(mx0, __shfl_xor_sync(0xffffffffu, mx0, 1));
            mx0 = fmaxf(mx0, __shfl_xor_sync(0xffffffffu, mx0, 2));
            mx1 = fmaxf(mx1, __shfl_xor_sync(0xffffffffu, mx1, 1));
            mx1 = fmaxf(mx1, __shfl_xor_sync(0xffffffffu, mx1, 2));
            const float nm0 = fmaxf(m0, mx0), nm1 = fmaxf(m1, mx1);

            float sum0 = 0.f, sum1 = 0.f;
#pragma unroll
            for (int nf = 0; nf < 8; nf++) {
                sf[nf][0] = __expf(sf[nf][0] - nm0);
                sf[nf][1] = __expf(sf[nf][1] - nm0);
                sf[nf][2] = __expf(sf[nf][2] - nm1);
                sf[nf][3] = __expf(sf[nf][3] - nm1);
                sum0 += sf[nf][0] + sf[nf][1];
                sum1 += sf[nf][2] + sf[nf][3];
            }
            sum0 += __shfl_xor_sync(0xffffffffu, sum0, 1);
            sum0 += __shfl_xor_sync(0xffffffffu, sum0, 2);
            sum1 += __shfl_xor_sync(0xffffffffu, sum1, 1);
            sum1 += __shfl_xor_sync(0xffffffffu, sum1, 2);

            const float sc0 = __expf(m0 - nm0), sc1 = __expf(m1 - nm1);
            l0 = l0 * sc0 + sum0; l1 = l1 * sc1 + sum1;
            m0 = nm0; m1 = nm1;

            // P (rounded) to its own buffer; C cols are 2t,2t+1 (unpermuted)
#pragma unroll
            for (int nf = 0; nf < 8; nf++) {
                int c0 = nf * 8 + 2 * t;
                Ps[row0 * 68 + c0    ] = f2tff(sf[nf][0]);
                Ps[row0 * 68 + c0 + 1] = f2tff(sf[nf][1]);
                Ps[row1 * 68 + c0    ] = f2tff(sf[nf][2]);
                Ps[row1 * 68 + c0 + 1] = f2tff(sf[nf][3]);
            }
            __syncwarp();   // PV A-fragments read only this warp's 16 rows

            // rescale O, then O += P V (standard slots, stride-72 V)
#pragma unroll
            for (int nf = 0; nf < 8; nf++) {
                of[nf][0] *= sc0; of[nf][1] *= sc0; of[nf][2] *= sc1; of[nf][3] *= sc1;
            }
#pragma unroll
            for (int kk = 0; kk < 8; kk++) {
                unsigned a0 = __float_as_uint(Ps[row0 * 68 + kk * 8 + t    ]);
                unsigned a1 = __float_as_uint(Ps[row1 * 68 + kk * 8 + t    ]);
                unsigned a2 = __float_as_uint(Ps[row0 * 68 + kk * 8 + t + 4]);
                unsigned a3 = __float_as_uint(Ps[row1 * 68 + kk * 8 + t + 4]);
#pragma unroll
                for (int nf = 0; nf < 8; nf++) {
                    unsigned b0 = __float_as_uint(Vs[(kk * 8 + t    ) * 72 + nf * 8 + g]);
                    unsigned b1 = __float_as_uint(Vs[(kk * 8 + t + 4) * 72 + nf * 8 + g]);
                    mma8(of[nf], a0, a1, a2, a3, b0, b1);
                }
            }
            __syncthreads();   // done with Ks/Vs before next issue overwrites
        }

        // normalize and write (rounded: gemm<1> consumes raw)
        const float il0 = 1.f / l0, il1 = 1.f / l1;
        const int sq0 = Q * 128 + row0, sq1 = Q * 128 + row1;
#pragma unroll
        for (int nf = 0; nf < 8; nf++) {
            int col = nf * 8 + 2 * t;
            float2 v0; v0.x = f2tff(of[nf][0] * il0); v0.y = f2tff(of[nf][1] * il0);
            float2 v1; v1.x = f2tff(of[nf][2] * il1); v1.y = f2tff(of[nf][3] * il1);
            *reinterpret_cast<float2*>(&g_ab[(((size_t)b * SEQ + sq0) * HEADS + h) * HD + col]) = v0;
            *reinterpret_cast<float2*>(&g_ab[(((size_t)b * SEQ + sq1) * HEADS + h) * HD + col]) = v1;
        }
    }
}

// ---------------- launch ----------------
extern "C" void kernel_launch(void* const* d_in, const int* in_sizes, int n_in,
                              void* d_out, int out_size)
{
    const float* x    = (const float*)d_in[0];
    const float* Wqkv = (const float*)d_in[1];
    const float* bqkv = (const float*)d_in[2];
    const float* Wd   = (const float*)d_in[3];
    const float* bd   = (const float*)d_in[4];
    const int*   mask = (const int*)d_in[5];
    float* out = (float*)d_out;

    cudaFuncSetAttribute(gemm_kernel<0>, cudaFuncAttributeMaxDynamicSharedMemorySize, GEMM_SMEM_BYTES);
    cudaFuncSetAttribute(gemm_kernel<1>, cudaFuncAttributeMaxDynamicSharedMemorySize, GEMM_SMEM_BYTES);
    cudaFuncSetAttribute(fa_kernel,      cudaFuncAttributeMaxDynamicSharedMemorySize, FA_SMEM_BYTES);

    static float* wq_dev = nullptr;
    static float* wd_dev = nullptr;
    if (!wq_dev) {
        cudaGetSymbolAddress((void**)&wq_dev, g_wqr);
        cudaGetSymbolAddress((void**)&wd_dev, g_wdr);
    }

    round_kernel<<<1024, 256>>>(x, Wqkv, Wd);

    gemm_kernel<0><<<dim3(N_QKV / 128, MTOT / 128), 256, GEMM_SMEM_BYTES>>>(
        wq_dev, bqkv, nullptr, MTOT, N_QKV, DMODEL);

    fa_kernel<<<dim3(8, NB * HEADS), 256, FA_SMEM_BYTES>>>(mask);

    gemm_kernel<1><<<dim3(DMODEL / 128, MTOT / 128), 256, GEMM_SMEM_BYTES>>>(
        wd_dev, bd, out, MTOT, DMODEL, DMODEL);
}